// round 2
// baseline (speedup 1.0000x reference)
#include <cuda_runtime.h>
#include <cuda_fp16.h>
#include <cstdint>
#include <math.h>

#define BATCH 2
#define NPTS  4096
#define CDIM  128
#define TOPK  8
#define ITERS 15
#define CSTRIDE 4112   // padded stride for r/c vectors (16B-aligned per batch)

// ---------------------------------------------------------------------------
// Device scratch (no runtime allocations allowed)
// ---------------------------------------------------------------------------
__device__ __half g_E[(size_t)BATCH * NPTS * NPTS];   // exp(scores), fp16, 67 MB
__device__ float  g_nA[BATCH * NPTS * CDIM];
__device__ float  g_nB[BATCH * NPTS * CDIM];
__device__ float  g_r[BATCH * CSTRIDE];
__device__ float  g_c[BATCH * CSTRIDE];
__device__ float  g_posBx[BATCH * NPTS];
__device__ float  g_posBy[BATCH * NPTS];
__device__ float  g_conf[BATCH * NPTS];
__device__ float  g_base[BATCH * NPTS * 2];
__device__ int    g_tki[BATCH * NPTS * TOPK];
__device__ float  g_tkl[BATCH * NPTS * TOPK];
__device__ float  g_geo[BATCH * NPTS * TOPK];
__device__ float  g_params[4];   // 0: inv_temp, 1: exp(ds), 2: gw

// ---------------------------------------------------------------------------
// FMA-pipe exp (no MUFU). Valid |x| <= ~80, rel err ~1e-7.
// ---------------------------------------------------------------------------
__device__ __forceinline__ float fexpf(float x) {
    float t = x * 1.4426950408889634f;          // x * log2(e)
    float z = t + 12582912.0f;                  // round-to-nearest
    int   ni = __float_as_int(z);
    float n  = z - 12582912.0f;
    float f  = t - n;                           // [-0.5, 0.5]
    float p = 1.5403530e-4f;
    p = fmaf(p, f, 1.33335581e-3f);
    p = fmaf(p, f, 9.61812911e-3f);
    p = fmaf(p, f, 5.55041087e-2f);
    p = fmaf(p, f, 2.40226507e-1f);
    p = fmaf(p, f, 6.93147181e-1f);
    p = fmaf(p, f, 1.0f);
    int e = (ni & 0x7FFFFF) - 0x400000;
    float s = __int_as_float((e + 127) << 23);
    return p * s;
}

// ---------------------------------------------------------------------------
// Prep: scalars, c init (exp(v=0)=1), pos_B channel split
// ---------------------------------------------------------------------------
__global__ void prep_kernel(const float* __restrict__ dust,
                            const float* __restrict__ geow,
                            const float* __restrict__ temp,
                            const float* __restrict__ posB) {
    int t = blockIdx.x * 256 + threadIdx.x;
    if (t == 0) {
        float tr = temp[0];
        g_params[0] = 1.0f / tr;
        float tc = fminf(fmaxf(tr, 0.2f), 10.0f);
        float ds = fminf(fmaxf(dust[0] / tc, -50.0f), 50.0f);
        g_params[1] = expf(ds);
        g_params[2] = fminf(fmaxf(geow[0], 0.0f), 2.0f);
    }
    if (t < BATCH * CSTRIDE) g_c[t] = 1.0f;
    if (t < BATCH * NPTS) {
        g_posBx[t] = posB[2 * t];
        g_posBy[t] = posB[2 * t + 1];
    }
}

// ---------------------------------------------------------------------------
// L2-normalize features: one warp per row
// ---------------------------------------------------------------------------
__global__ void norm_kernel(const float* __restrict__ fA, const float* __restrict__ fB) {
    int wg   = blockIdx.x * 8 + (threadIdx.x >> 5);
    int lane = threadIdx.x & 31;
    int tensor = wg >> 13;
    int row    = wg & 8191;
    const float* src = tensor ? fB : fA;
    float*       dst = tensor ? g_nB : g_nA;
    float4 v = *reinterpret_cast<const float4*>(src + (size_t)row * CDIM + lane * 4);
    float ss = v.x * v.x + v.y * v.y + v.z * v.z + v.w * v.w;
#pragma unroll
    for (int o = 16; o; o >>= 1) ss += __shfl_xor_sync(0xffffffffu, ss, o);
    float inv = 1.0f / fmaxf(sqrtf(ss), 1e-12f);
    v.x *= inv; v.y *= inv; v.z *= inv; v.w *= inv;
    *reinterpret_cast<float4*>(dst + (size_t)row * CDIM + lane * 4) = v;
}

// ---------------------------------------------------------------------------
// GEMM fused with clamp + exp -> fp16 E. 64x64 tiles, 4x4 microtiles.
// ---------------------------------------------------------------------------
__global__ void gemm_exp_kernel() {
    int b  = blockIdx.z;
    int i0 = blockIdx.y * 64;
    int j0 = blockIdx.x * 64;
    const float* A  = g_nA + (size_t)b * NPTS * CDIM;
    const float* Bt = g_nB + (size_t)b * NPTS * CDIM;

    __shared__ float As[32 * 68];
    __shared__ float Bs[32 * 68];

    int tid = threadIdx.x;
    int tx = tid & 15, ty = tid >> 4;
    float acc[4][4];
#pragma unroll
    for (int i = 0; i < 4; i++)
#pragma unroll
        for (int j = 0; j < 4; j++) acc[i][j] = 0.0f;

    for (int kb = 0; kb < CDIM; kb += 32) {
#pragma unroll
        for (int e = 0; e < 8; e++) {
            int idx = tid + e * 256;
            int m = idx >> 5, k = idx & 31;
            As[k * 68 + m] = A[(size_t)(i0 + m) * CDIM + kb + k];
            Bs[k * 68 + m] = Bt[(size_t)(j0 + m) * CDIM + kb + k];
        }
        __syncthreads();
#pragma unroll
        for (int kk = 0; kk < 32; kk++) {
            float4 av = *reinterpret_cast<const float4*>(As + kk * 68 + ty * 4);
            float4 bv = *reinterpret_cast<const float4*>(Bs + kk * 68 + tx * 4);
            float aa[4] = {av.x, av.y, av.z, av.w};
            float bb[4] = {bv.x, bv.y, bv.z, bv.w};
#pragma unroll
            for (int i = 0; i < 4; i++)
#pragma unroll
                for (int j = 0; j < 4; j++)
                    acc[i][j] = fmaf(aa[i], bb[j], acc[i][j]);
        }
        __syncthreads();
    }

    float itp = g_params[0];
    __half* Eb = g_E + ((size_t)b << 24);
#pragma unroll
    for (int i = 0; i < 4; i++) {
        int row = i0 + ty * 4 + i;
        float e0 = fexpf(fminf(fmaxf(acc[i][0] * itp, -50.0f), 50.0f));
        float e1 = fexpf(fminf(fmaxf(acc[i][1] * itp, -50.0f), 50.0f));
        float e2 = fexpf(fminf(fmaxf(acc[i][2] * itp, -50.0f), 50.0f));
        float e3 = fexpf(fminf(fmaxf(acc[i][3] * itp, -50.0f), 50.0f));
        __half2* p = reinterpret_cast<__half2*>(Eb + (size_t)row * NPTS + j0 + tx * 4);
        p[0] = __floats2half2_rn(e0, e1);
        p[1] = __floats2half2_rn(e2, e3);
    }
}

// ---------------------------------------------------------------------------
// Sinkhorn row pass: r = mu / (E c + dust terms).  blockIdx.x in [0,4096]
// ---------------------------------------------------------------------------
__global__ void row_pass() {
    int b = blockIdx.y, i = blockIdx.x, tid = threadIdx.x;
    const float* cb = g_c + b * CSTRIDE;
    float sum = 0.0f;
    if (i < NPTS) {
        const __half* Er = g_E + ((size_t)b << 24) + ((size_t)i << 12);
#pragma unroll
        for (int it = 0; it < 2; ++it) {
            int j = it * 2048 + tid * 8;
            uint4 ev = *reinterpret_cast<const uint4*>(Er + j);
            const __half2* hp = reinterpret_cast<const __half2*>(&ev);
            float4 c0 = *reinterpret_cast<const float4*>(cb + j);
            float4 c1 = *reinterpret_cast<const float4*>(cb + j + 4);
            float2 f0 = __half22float2(hp[0]);
            float2 f1 = __half22float2(hp[1]);
            float2 f2 = __half22float2(hp[2]);
            float2 f3 = __half22float2(hp[3]);
            sum = fmaf(f0.x, c0.x, sum); sum = fmaf(f0.y, c0.y, sum);
            sum = fmaf(f1.x, c0.z, sum); sum = fmaf(f1.y, c0.w, sum);
            sum = fmaf(f2.x, c1.x, sum); sum = fmaf(f2.y, c1.y, sum);
            sum = fmaf(f3.x, c1.z, sum); sum = fmaf(f3.y, c1.w, sum);
        }
    } else {
        for (int j = tid; j < NPTS; j += 256) sum += cb[j];
    }
#pragma unroll
    for (int o = 16; o; o >>= 1) sum += __shfl_xor_sync(0xffffffffu, sum, o);
    __shared__ float red[8];
    if ((tid & 31) == 0) red[tid >> 5] = sum;
    __syncthreads();
    if (tid == 0) {
        float tot = 0.0f;
#pragma unroll
        for (int w = 0; w < 8; w++) tot += red[w];
        float ed = g_params[1];
        float cN = cb[NPTS];
        float denom, num;
        if (i < NPTS) { denom = tot + ed * cN;  num = 1.0f / 8192.0f; }
        else          { denom = ed * tot + cN;  num = 0.5f; }
        g_r[b * CSTRIDE + i] = num / denom;
    }
}

// ---------------------------------------------------------------------------
// Sinkhorn col pass: c = nu / (E^T r + dust terms). 64 cols/block + dust block
// ---------------------------------------------------------------------------
__global__ void col_pass() {
    int b = blockIdx.y, tid = threadIdx.x;
    const float* rb = g_r + b * CSTRIDE;
    __shared__ float rs[NPTS];
    for (int k = tid; k < NPTS; k += 256) rs[k] = rb[k];
    __syncthreads();
    float ed = g_params[1];
    if (blockIdx.x < 64) {
        int n0 = blockIdx.x * 64;
        int tx = tid & 31, ty = tid >> 5;
        const __half* Eb = g_E + ((size_t)b << 24) + n0 + 2 * tx;
        float ax = 0.0f, ay = 0.0f;
#pragma unroll 8
        for (int i2 = ty; i2 < NPTS; i2 += 8) {
            __half2 e2 = *reinterpret_cast<const __half2*>(Eb + ((size_t)i2 << 12));
            float ri = rs[i2];
            float2 f = __half22float2(e2);
            ax = fmaf(f.x, ri, ax);
            ay = fmaf(f.y, ri, ay);
        }
        __shared__ float px[8][32], py[8][32];
        px[ty][tx] = ax; py[ty][tx] = ay;
        __syncthreads();
#pragma unroll
        for (int s = 4; s; s >>= 1) {
            if (ty < s) { px[ty][tx] += px[ty + s][tx]; py[ty][tx] += py[ty + s][tx]; }
            __syncthreads();
        }
        if (ty == 0) {
            float d = ed * rb[NPTS];
            float* cc = g_c + b * CSTRIDE;
            cc[n0 + 2 * tx]     = (1.0f / 8192.0f) / (px[0][tx] + d);
            cc[n0 + 2 * tx + 1] = (1.0f / 8192.0f) / (py[0][tx] + d);
        }
    } else {  // dustbin column
        float s = 0.0f;
        for (int i2 = tid; i2 < NPTS; i2 += 256) s += rs[i2];
#pragma unroll
        for (int o = 16; o; o >>= 1) s += __shfl_xor_sync(0xffffffffu, s, o);
        __shared__ float red[8];
        if ((tid & 31) == 0) red[tid >> 5] = s;
        __syncthreads();
        if (tid == 0) {
            float tot = 0.0f;
#pragma unroll
            for (int w = 0; w < 8; w++) tot += red[w];
            g_c[b * CSTRIDE + NPTS] = 0.5f / (ed * tot + rb[NPTS]);
        }
    }
}

// ---------------------------------------------------------------------------
// Per-row stats: P = E r c; row mass, base expected pos, top-8, confidence
// ---------------------------------------------------------------------------
__global__ void stats_kernel() {
    int b = blockIdx.y, i = blockIdx.x, tid = threadIdx.x;
    const __half* Er = g_E + ((size_t)b << 24) + ((size_t)i << 12);
    const float* cb  = g_c + b * CSTRIDE;
    const float* pxb = g_posBx + b * NPTS;
    const float* pyb = g_posBy + b * NPTS;
    float rp = g_r[b * CSTRIDE + i];

    float sm = 0.0f, sx = 0.0f, sy = 0.0f;
    float tv[8]; int tix[8];
#pragma unroll
    for (int t = 0; t < 8; t++) { tv[t] = -1.0f; tix[t] = 0x7fffffff; }

#pragma unroll
    for (int it = 0; it < 2; ++it) {
        int j = it * 2048 + tid * 8;
        uint4 ev = *reinterpret_cast<const uint4*>(Er + j);
        const __half2* hp = reinterpret_cast<const __half2*>(&ev);
        float4 c0 = *reinterpret_cast<const float4*>(cb + j);
        float4 c1 = *reinterpret_cast<const float4*>(cb + j + 4);
        float4 x0 = *reinterpret_cast<const float4*>(pxb + j);
        float4 x1 = *reinterpret_cast<const float4*>(pxb + j + 4);
        float4 y0 = *reinterpret_cast<const float4*>(pyb + j);
        float4 y1 = *reinterpret_cast<const float4*>(pyb + j + 4);
        float2 f0 = __half22float2(hp[0]);
        float2 f1 = __half22float2(hp[1]);
        float2 f2 = __half22float2(hp[2]);
        float2 f3 = __half22float2(hp[3]);
        float ps[8] = {f0.x, f0.y, f1.x, f1.y, f2.x, f2.y, f3.x, f3.y};
        float cs[8] = {c0.x, c0.y, c0.z, c0.w, c1.x, c1.y, c1.z, c1.w};
        float xs[8] = {x0.x, x0.y, x0.z, x0.w, x1.x, x1.y, x1.z, x1.w};
        float ys[8] = {y0.x, y0.y, y0.z, y0.w, y1.x, y1.y, y1.z, y1.w};
#pragma unroll
        for (int q = 0; q < 8; q++) {
            float P  = ps[q] * rp * cs[q];
            float ot = fminf(P, 1.0f);
            sm += ot;
            sx = fmaf(ot, xs[q], sx);
            sy = fmaf(ot, ys[q], sy);
            int jj = j + q;
            if (ot > tv[7] || (ot == tv[7] && jj < tix[7])) {
                tv[7] = ot; tix[7] = jj;
#pragma unroll
                for (int q2 = 7; q2 > 0; --q2) {
                    bool sw = (tv[q2] > tv[q2 - 1]) ||
                              (tv[q2] == tv[q2 - 1] && tix[q2] < tix[q2 - 1]);
                    if (sw) {
                        float fv = tv[q2]; tv[q2] = tv[q2 - 1]; tv[q2 - 1] = fv;
                        int ii = tix[q2]; tix[q2] = tix[q2 - 1]; tix[q2 - 1] = ii;
                    }
                }
            }
        }
    }

    float s0 = sm, s1 = sx, s2 = sy;
#pragma unroll
    for (int o = 16; o; o >>= 1) {
        s0 += __shfl_xor_sync(0xffffffffu, s0, o);
        s1 += __shfl_xor_sync(0xffffffffu, s1, o);
        s2 += __shfl_xor_sync(0xffffffffu, s2, o);
    }
    __shared__ float redm[8], redx[8], redy[8];
    if ((tid & 31) == 0) { redm[tid >> 5] = s0; redx[tid >> 5] = s1; redy[tid >> 5] = s2; }

    __shared__ float sv[2048];
    __shared__ int   si[2048];
#pragma unroll
    for (int t = 0; t < 8; t++) { sv[tid * 8 + t] = tv[t]; si[tid * 8 + t] = tix[t]; }
    __syncthreads();

    for (int step = 128; step >= 1; step >>= 1) {
        if (tid < step) {
            int ia = tid * 8, ib = (tid + step) * 8;
            float av[8], bv[8], ov[8]; int ai[8], bi[8], oi[8];
#pragma unroll
            for (int t = 0; t < 8; t++) {
                av[t] = sv[ia + t]; ai[t] = si[ia + t];
                bv[t] = sv[ib + t]; bi[t] = si[ib + t];
            }
            int pa = 0, pb = 0;
#pragma unroll
            for (int o = 0; o < 8; o++) {
                bool ta = (av[pa] > bv[pb]) || (av[pa] == bv[pb] && ai[pa] <= bi[pb]);
                if (ta) { ov[o] = av[pa]; oi[o] = ai[pa]; pa++; }
                else    { ov[o] = bv[pb]; oi[o] = bi[pb]; pb++; }
            }
#pragma unroll
            for (int t = 0; t < 8; t++) { sv[ia + t] = ov[t]; si[ia + t] = oi[t]; }
        }
        __syncthreads();
    }

    if (tid == 0) {
        float smT = 0, sxT = 0, syT = 0;
#pragma unroll
        for (int w = 0; w < 8; w++) { smT += redm[w]; sxT += redx[w]; syT += redy[w]; }
        float rmass = fmaxf(smT, 1e-8f);
        float valid = fminf(fmaxf(rmass * 8192.0f, 0.0f), 1.0f);
        float top1 = sv[0], top2 = sv[1];
        float pr = fminf(fmaxf(top1 / rmass, 0.0f), 1.0f);
        float pm = fminf(fmaxf((top1 - top2) / rmass, 0.0f), 1.0f);
        float conf = fminf(fmaxf((0.6f * pr + 0.4f * pm) * valid, 0.0f), 1.0f);
        int o = b * NPTS + i;
        g_conf[o] = conf;
        g_base[o * 2]     = sxT / rmass;
        g_base[o * 2 + 1] = syT / rmass;
#pragma unroll
        for (int k = 0; k < 8; k++) {
            g_tki[o * 8 + k] = si[k];
            g_tkl[o * 8 + k] = logf(fmaxf(sv[k], 1e-38f));
        }
    }
}

// ---------------------------------------------------------------------------
// Geo validation: per (b,k) field, 7x7 variance pooling (count_include_pad=F)
// ---------------------------------------------------------------------------
__global__ void geo_kernel(const float* __restrict__ posA) {
    int bk = blockIdx.x;
    int b = bk >> 3, k = bk & 7;
    int tid = threadIdx.x;
    __shared__ float dx[NPTS], dy[NPTS];   // 32 KB
    for (int n = tid; n < NPTS; n += 256) {
        int idx = g_tki[(b * NPTS + n) * 8 + k];
        float ax = posA[(size_t)(b * NPTS + n) * 2];
        float ay = posA[(size_t)(b * NPTS + n) * 2 + 1];
        dx[n] = g_posBx[b * NPTS + idx] - ax;
        dy[n] = g_posBy[b * NPTS + idx] - ay;
    }
    __syncthreads();
    for (int n = tid; n < NPTS; n += 256) {
        int h = n >> 6, w = n & 63;
        int h0 = max(h - 3, 0), h1 = min(h + 3, 63);
        int w0 = max(w - 3, 0), w1 = min(w + 3, 63);
        float sxv = 0, syv = 0, sxx = 0, syy = 0;
        for (int hh = h0; hh <= h1; hh++) {
            int base = hh * 64;
            for (int ww = w0; ww <= w1; ww++) {
                float vx = dx[base + ww], vy = dy[base + ww];
                sxv += vx; syv += vy;
                sxx = fmaf(vx, vx, sxx);
                syy = fmaf(vy, vy, syy);
            }
        }
        float inv = 1.0f / (float)((h1 - h0 + 1) * (w1 - w0 + 1));
        float mx = sxv * inv, my = syv * inv;
        float vx = fmaxf(sxx * inv - mx * mx, 0.0f);
        float vy = fmaxf(syy * inv - my * my, 0.0f);
        g_geo[(b * NPTS + n) * 8 + k] = 1.0f / (1.0f + (vx + vy) * 100.0f);
    }
}

// ---------------------------------------------------------------------------
// Final: softmax over (logp + gw*geo), refined pos, confidence blend
// ---------------------------------------------------------------------------
__global__ void final_kernel(float* __restrict__ out) {
    int t = blockIdx.x * 128 + threadIdx.x;   // < B*N
    int b = t >> 12, n = t & 4095;
    int o = b * NPTS + n;
    float gwv = g_params[2];
    float lc[8]; int id[8];
    float m = -1e30f;
#pragma unroll
    for (int k = 0; k < 8; k++) {
        lc[k] = g_tkl[o * 8 + k] + gwv * g_geo[o * 8 + k];
        id[k] = g_tki[o * 8 + k];
        m = fmaxf(m, lc[k]);
    }
    float ws = 0, rx = 0, ry = 0;
#pragma unroll
    for (int k = 0; k < 8; k++) {
        float w = fexpf(fmaxf(lc[k] - m, -80.0f));
        ws += w;
        rx = fmaf(w, g_posBx[b * NPTS + id[k]], rx);
        ry = fmaf(w, g_posBy[b * NPTS + id[k]], ry);
    }
    rx /= ws; ry /= ws;
    float conf = g_conf[o];
    out[o * 2]     = conf * rx + (1.0f - conf) * g_base[o * 2];
    out[o * 2 + 1] = conf * ry + (1.0f - conf) * g_base[o * 2 + 1];
}

// ---------------------------------------------------------------------------
extern "C" void kernel_launch(void* const* d_in, const int* in_sizes, int n_in,
                              void* d_out, int out_size) {
    const float* fA   = (const float*)d_in[0];
    const float* fB   = (const float*)d_in[1];
    const float* pA   = (const float*)d_in[2];
    const float* pB   = (const float*)d_in[3];
    const float* dust = (const float*)d_in[4];
    const float* geow = (const float*)d_in[5];
    const float* temp = (const float*)d_in[6];
    float* out = (float*)d_out;

    prep_kernel<<<33, 256>>>(dust, geow, temp, pB);
    norm_kernel<<<2048, 256>>>(fA, fB);
    gemm_exp_kernel<<<dim3(64, 64, BATCH), 256>>>();
    for (int it = 0; it < ITERS; ++it) {
        row_pass<<<dim3(NPTS + 1, BATCH), 256>>>();
        col_pass<<<dim3(65, BATCH), 256>>>();
    }
    stats_kernel<<<dim3(NPTS, BATCH), 256>>>();
    geo_kernel<<<BATCH * TOPK, 256>>>(pA);
    final_kernel<<<64, 128>>>(out);
}

// round 3
// speedup vs baseline: 1.5883x; 1.5883x over previous
#include <cuda_runtime.h>
#include <cuda_fp16.h>
#include <cstdint>
#include <math.h>

#define BATCH 2
#define NPTS  4096
#define CDIM  128
#define TOPK  8
#define ITERS 15
#define CSTRIDE 4112

// ---------------------------------------------------------------------------
// Device scratch
// ---------------------------------------------------------------------------
__device__ __half g_E[(size_t)BATCH * NPTS * NPTS];   // exp(scores), 67 MB
__device__ __half g_hA[BATCH * NPTS * CDIM];
__device__ __half g_hB[BATCH * NPTS * CDIM];
__device__ float  g_r[BATCH * CSTRIDE];
__device__ float  g_c[BATCH * CSTRIDE];
__device__ float  g_colsum[BATCH * NPTS];
__device__ float  g_rsum[BATCH];
__device__ float  g_posBx[BATCH * NPTS];
__device__ float  g_posBy[BATCH * NPTS];
__device__ float  g_conf[BATCH * NPTS];
__device__ float  g_base[BATCH * NPTS * 2];
__device__ int    g_tki[BATCH * NPTS * TOPK];
__device__ float  g_tkl[BATCH * NPTS * TOPK];
__device__ float  g_geo[BATCH * NPTS * TOPK];
__device__ float  g_params[4];

// ---------------------------------------------------------------------------
// FMA-pipe exp (no MUFU)
// ---------------------------------------------------------------------------
__device__ __forceinline__ float fexpf(float x) {
    float t = x * 1.4426950408889634f;
    float z = t + 12582912.0f;
    int   ni = __float_as_int(z);
    float n  = z - 12582912.0f;
    float f  = t - n;
    float p = 1.5403530e-4f;
    p = fmaf(p, f, 1.33335581e-3f);
    p = fmaf(p, f, 9.61812911e-3f);
    p = fmaf(p, f, 5.55041087e-2f);
    p = fmaf(p, f, 2.40226507e-1f);
    p = fmaf(p, f, 6.93147181e-1f);
    p = fmaf(p, f, 1.0f);
    int e = (ni & 0x7FFFFF) - 0x400000;
    float s = __int_as_float((e + 127) << 23);
    return p * s;
}

// ---------------------------------------------------------------------------
// Prep
// ---------------------------------------------------------------------------
__global__ void prep_kernel(const float* __restrict__ dust,
                            const float* __restrict__ geow,
                            const float* __restrict__ temp,
                            const float* __restrict__ posB) {
    int t = blockIdx.x * 256 + threadIdx.x;
    if (t == 0) {
        float tr = temp[0];
        g_params[0] = 1.0f / tr;
        float tc = fminf(fmaxf(tr, 0.2f), 10.0f);
        float ds = fminf(fmaxf(dust[0] / tc, -50.0f), 50.0f);
        g_params[1] = expf(ds);
        g_params[2] = fminf(fmaxf(geow[0], 0.0f), 2.0f);
    }
    if (t < BATCH * CSTRIDE) g_c[t] = 1.0f;
    if (t < BATCH * NPTS) {
        g_colsum[t] = 0.0f;
        g_posBx[t] = posB[2 * t];
        g_posBy[t] = posB[2 * t + 1];
    }
    if (t < BATCH) g_rsum[t] = 0.0f;
}

// ---------------------------------------------------------------------------
// L2-normalize -> fp16 features
// ---------------------------------------------------------------------------
__global__ void norm_kernel(const float* __restrict__ fA, const float* __restrict__ fB) {
    int wg   = blockIdx.x * 8 + (threadIdx.x >> 5);
    int lane = threadIdx.x & 31;
    int tensor = wg >> 13;
    int row    = wg & 8191;
    const float* src = tensor ? fB : fA;
    __half*      dst = tensor ? g_hB : g_hA;
    float4 v = *reinterpret_cast<const float4*>(src + (size_t)row * CDIM + lane * 4);
    float ss = v.x * v.x + v.y * v.y + v.z * v.z + v.w * v.w;
#pragma unroll
    for (int o = 16; o; o >>= 1) ss += __shfl_xor_sync(0xffffffffu, ss, o);
    float inv = 1.0f / fmaxf(sqrtf(ss), 1e-12f);
    __half2 h01 = __floats2half2_rn(v.x * inv, v.y * inv);
    __half2 h23 = __floats2half2_rn(v.z * inv, v.w * inv);
    uint2 u;
    u.x = *reinterpret_cast<uint32_t*>(&h01);
    u.y = *reinterpret_cast<uint32_t*>(&h23);
    *reinterpret_cast<uint2*>(dst + (size_t)row * CDIM + lane * 4) = u;
}

// ---------------------------------------------------------------------------
// Tensor-core GEMM + exp epilogue.  128x128 block tile, 8 warps (4M x 2N),
// warp tile 32x64 via mma.m16n8k16 f16->f32.  K=128 in 2 chunks of 64.
// ---------------------------------------------------------------------------
__device__ __forceinline__ void ldsm4(uint32_t* r, uint32_t addr) {
    asm volatile("ldmatrix.sync.aligned.m8n8.x4.shared.b16 {%0,%1,%2,%3}, [%4];\n"
        : "=r"(r[0]), "=r"(r[1]), "=r"(r[2]), "=r"(r[3]) : "r"(addr));
}
__device__ __forceinline__ void mma16816(float* c, const uint32_t* a, const uint32_t* b) {
    asm volatile("mma.sync.aligned.m16n8k16.row.col.f32.f16.f16.f32 "
        "{%0,%1,%2,%3}, {%4,%5,%6,%7}, {%8,%9}, {%0,%1,%2,%3};\n"
        : "+f"(c[0]), "+f"(c[1]), "+f"(c[2]), "+f"(c[3])
        : "r"(a[0]), "r"(a[1]), "r"(a[2]), "r"(a[3]), "r"(b[0]), "r"(b[1]));
}

#define SMK 72    // padded k-stride (halfs) for tiles: 144B, ldmatrix conflict-free
#define SOUTS 136 // padded out stride (halfs): 272B

__global__ __launch_bounds__(256) void gemm_exp_kernel() {
    int b  = blockIdx.z;
    int i0 = blockIdx.y * 128;
    int j0 = blockIdx.x * 128;
    const __half* A  = g_hA + (size_t)b * NPTS * CDIM;
    const __half* Bm = g_hB + (size_t)b * NPTS * CDIM;

    __shared__ __align__(16) __half smem[2 * 128 * SMK];   // 36.9 KB
    __half* sA = smem;
    __half* sB = smem + 128 * SMK;

    int tid = threadIdx.x;
    int w = tid >> 5, lane = tid & 31;
    int wm = (w >> 1) * 32, wn = (w & 1) * 64;
    float itp = g_params[0];

    float acc[2][8][4];
#pragma unroll
    for (int mt = 0; mt < 2; mt++)
#pragma unroll
        for (int nt = 0; nt < 8; nt++)
#pragma unroll
            for (int q = 0; q < 4; q++) acc[mt][nt][q] = 0.0f;

#pragma unroll
    for (int kb = 0; kb < CDIM; kb += 64) {
        if (kb) __syncthreads();
#pragma unroll
        for (int e = 0; e < 4; e++) {
            int idx = tid + e * 256;          // 1024 uint4 per matrix
            int r = idx >> 3, c8 = idx & 7;
            *reinterpret_cast<uint4*>(sA + r * SMK + c8 * 8) =
                *reinterpret_cast<const uint4*>(A + (size_t)(i0 + r) * CDIM + kb + c8 * 8);
            *reinterpret_cast<uint4*>(sB + r * SMK + c8 * 8) =
                *reinterpret_cast<const uint4*>(Bm + (size_t)(j0 + r) * CDIM + kb + c8 * 8);
        }
        __syncthreads();

#pragma unroll
        for (int ks = 0; ks < 4; ks++) {
            int k0 = ks * 16;
            uint32_t afr[2][4];
#pragma unroll
            for (int mt = 0; mt < 2; mt++) {
                int row = wm + mt * 16 + (lane & 15);
                int col = k0 + ((lane >> 4) << 3);
                uint32_t addr = (uint32_t)__cvta_generic_to_shared(sA + row * SMK + col);
                ldsm4(afr[mt], addr);
            }
            uint32_t bfr[8][2];
#pragma unroll
            for (int p = 0; p < 4; p++) {
                int l4 = lane & 7, g = lane >> 3;
                int row = wn + p * 16 + ((g >> 1) << 3) + l4;
                int col = k0 + ((g & 1) << 3);
                uint32_t addr = (uint32_t)__cvta_generic_to_shared(sB + row * SMK + col);
                uint32_t t4[4];
                ldsm4(t4, addr);
                bfr[2 * p][0] = t4[0]; bfr[2 * p][1] = t4[1];
                bfr[2 * p + 1][0] = t4[2]; bfr[2 * p + 1][1] = t4[3];
            }
#pragma unroll
            for (int mt = 0; mt < 2; mt++)
#pragma unroll
                for (int nt = 0; nt < 8; nt++)
                    mma16816(acc[mt][nt], afr[mt], bfr[nt]);
        }
    }
    __syncthreads();   // done reading tiles; reuse smem for epilogue staging

    __half* sO = smem;   // 128 x SOUTS halfs = 34.8 KB
#pragma unroll
    for (int mt = 0; mt < 2; mt++) {
#pragma unroll
        for (int nt = 0; nt < 8; nt++) {
            float e0 = fexpf(fminf(fmaxf(acc[mt][nt][0] * itp, -50.0f), 50.0f));
            float e1 = fexpf(fminf(fmaxf(acc[mt][nt][1] * itp, -50.0f), 50.0f));
            float e2 = fexpf(fminf(fmaxf(acc[mt][nt][2] * itp, -50.0f), 50.0f));
            float e3 = fexpf(fminf(fmaxf(acc[mt][nt][3] * itp, -50.0f), 50.0f));
            int row  = wm + mt * 16 + (lane >> 2);
            int colh = wn + nt * 8 + ((lane & 3) << 1);
            *reinterpret_cast<__half2*>(sO + row * SOUTS + colh)       = __floats2half2_rn(e0, e1);
            *reinterpret_cast<__half2*>(sO + (row + 8) * SOUTS + colh) = __floats2half2_rn(e2, e3);
        }
    }
    __syncthreads();

    __half* Eb = g_E + ((size_t)b << 24);
#pragma unroll
    for (int e = 0; e < 8; e++) {
        int idx = tid + e * 256;          // 2048 uint4
        int r = idx >> 4, c = idx & 15;
        *reinterpret_cast<uint4*>(Eb + (size_t)(i0 + r) * NPTS + j0 + c * 8) =
            *reinterpret_cast<uint4*>(sO + r * SOUTS + c * 8);
    }
}

// ---------------------------------------------------------------------------
// Fused Sinkhorn iteration: 64-row stripes; phase1 r = mu/(E c + ...),
// phase2 col partials E^T r (stripe re-read is L2-hot) -> atomic colsum.
// ---------------------------------------------------------------------------
__global__ __launch_bounds__(512) void sink_fused() {
    int b = blockIdx.y;
    int i0 = blockIdx.x * 64;
    int tid = threadIdx.x, w = tid >> 5, lane = tid & 31;
    __shared__ __align__(16) float cs[4100];
    __shared__ float rs[64];
    const float* cg = g_c + b * CSTRIDE;
    for (int t = tid; t < 4097; t += 512) cs[t] = cg[t];
    __syncthreads();
    float ed = g_params[1];
    const __half* Eb = g_E + ((size_t)b << 24);

    // phase 1: warp w handles rows i0 + 4w .. 4w+3
#pragma unroll
    for (int rr = 0; rr < 4; rr++) {
        int i = i0 + w * 4 + rr;
        const __half* Er = Eb + ((size_t)i << 12);
        float sum = 0.0f;
#pragma unroll 4
        for (int it = 0; it < 16; it++) {
            int j = it * 256 + lane * 8;
            uint4 ev = *reinterpret_cast<const uint4*>(Er + j);
            const __half2* hp = reinterpret_cast<const __half2*>(&ev);
            float4 c0 = *reinterpret_cast<const float4*>(cs + j);
            float4 c1 = *reinterpret_cast<const float4*>(cs + j + 4);
            float2 f0 = __half22float2(hp[0]);
            float2 f1 = __half22float2(hp[1]);
            float2 f2 = __half22float2(hp[2]);
            float2 f3 = __half22float2(hp[3]);
            sum = fmaf(f0.x, c0.x, sum); sum = fmaf(f0.y, c0.y, sum);
            sum = fmaf(f1.x, c0.z, sum); sum = fmaf(f1.y, c0.w, sum);
            sum = fmaf(f2.x, c1.x, sum); sum = fmaf(f2.y, c1.y, sum);
            sum = fmaf(f3.x, c1.z, sum); sum = fmaf(f3.y, c1.w, sum);
        }
#pragma unroll
        for (int o = 16; o; o >>= 1) sum += __shfl_xor_sync(0xffffffffu, sum, o);
        if (lane == 0) {
            float r = (1.0f / 8192.0f) / (sum + ed * cs[4096]);
            rs[w * 4 + rr] = r;
            g_r[b * CSTRIDE + i] = r;
        }
    }
    __syncthreads();
    if (tid < 64) {
        float v = rs[tid];
#pragma unroll
        for (int o = 16; o; o >>= 1) v += __shfl_xor_sync(0xffffffffu, v, o);
        if (lane == 0) atomicAdd(&g_rsum[b], v);
    }

    // phase 2: thread owns 8 cols j = tid*8..+7; stripe rows are L2-hot
    float a[8];
#pragma unroll
    for (int q = 0; q < 8; q++) a[q] = 0.0f;
    const __half* Ec = Eb + ((size_t)i0 << 12) + tid * 8;
#pragma unroll 4
    for (int i = 0; i < 64; i++) {
        uint4 ev = *reinterpret_cast<const uint4*>(Ec + ((size_t)i << 12));
        const __half2* hp = reinterpret_cast<const __half2*>(&ev);
        float r = rs[i];
        float2 f0 = __half22float2(hp[0]);
        float2 f1 = __half22float2(hp[1]);
        float2 f2 = __half22float2(hp[2]);
        float2 f3 = __half22float2(hp[3]);
        a[0] = fmaf(f0.x, r, a[0]); a[1] = fmaf(f0.y, r, a[1]);
        a[2] = fmaf(f1.x, r, a[2]); a[3] = fmaf(f1.y, r, a[3]);
        a[4] = fmaf(f2.x, r, a[4]); a[5] = fmaf(f2.y, r, a[5]);
        a[6] = fmaf(f3.x, r, a[6]); a[7] = fmaf(f3.y, r, a[7]);
    }
    float* col = g_colsum + b * NPTS + tid * 8;
#pragma unroll
    for (int q = 0; q < 8; q++) atomicAdd(col + q, a[q]);
}

// Finish: dust row r_M, c update, reset accumulators. One block per batch.
__global__ __launch_bounds__(1024) void sink_finish() {
    int b = blockIdx.x, tid = threadIdx.x;
    float* cc  = g_c + b * CSTRIDE;
    float* col = g_colsum + b * NPTS;
    float ed = g_params[1];
    float s = 0.0f;
#pragma unroll
    for (int q = 0; q < 4; q++) s += cc[tid + q * 1024];
#pragma unroll
    for (int o = 16; o; o >>= 1) s += __shfl_xor_sync(0xffffffffu, s, o);
    __shared__ float red[32];
    __shared__ float srm;
    if ((tid & 31) == 0) red[tid >> 5] = s;
    __syncthreads();
    if (tid == 0) {
        float sc = 0.0f;
#pragma unroll
        for (int ww = 0; ww < 32; ww++) sc += red[ww];
        float cN = cc[4096];
        srm = 0.5f / (ed * sc + cN);
    }
    __syncthreads();
    float rm = srm;
#pragma unroll
    for (int q = 0; q < 4; q++) {
        int j = tid + q * 1024;
        float v = col[j];
        cc[j] = (1.0f / 8192.0f) / (v + ed * rm);
        col[j] = 0.0f;
    }
    if (tid == 0) {
        cc[4096] = 0.5f / (ed * g_rsum[b] + rm);
        g_rsum[b] = 0.0f;
    }
}

// ---------------------------------------------------------------------------
// Per-row stats: P = E r c; row mass, base expected pos, top-8, confidence
// ---------------------------------------------------------------------------
__global__ void stats_kernel() {
    int b = blockIdx.y, i = blockIdx.x, tid = threadIdx.x;
    const __half* Er = g_E + ((size_t)b << 24) + ((size_t)i << 12);
    const float* cb  = g_c + b * CSTRIDE;
    const float* pxb = g_posBx + b * NPTS;
    const float* pyb = g_posBy + b * NPTS;
    float rp = g_r[b * CSTRIDE + i];

    float sm = 0.0f, sx = 0.0f, sy = 0.0f;
    float tv[8]; int tix[8];
#pragma unroll
    for (int t = 0; t < 8; t++) { tv[t] = -1.0f; tix[t] = 0x7fffffff; }

#pragma unroll
    for (int it = 0; it < 2; ++it) {
        int j = it * 2048 + tid * 8;
        uint4 ev = *reinterpret_cast<const uint4*>(Er + j);
        const __half2* hp = reinterpret_cast<const __half2*>(&ev);
        float4 c0 = *reinterpret_cast<const float4*>(cb + j);
        float4 c1 = *reinterpret_cast<const float4*>(cb + j + 4);
        float4 x0 = *reinterpret_cast<const float4*>(pxb + j);
        float4 x1 = *reinterpret_cast<const float4*>(pxb + j + 4);
        float4 y0 = *reinterpret_cast<const float4*>(pyb + j);
        float4 y1 = *reinterpret_cast<const float4*>(pyb + j + 4);
        float2 f0 = __half22float2(hp[0]);
        float2 f1 = __half22float2(hp[1]);
        float2 f2 = __half22float2(hp[2]);
        float2 f3 = __half22float2(hp[3]);
        float ps[8] = {f0.x, f0.y, f1.x, f1.y, f2.x, f2.y, f3.x, f3.y};
        float csv[8] = {c0.x, c0.y, c0.z, c0.w, c1.x, c1.y, c1.z, c1.w};
        float xs[8] = {x0.x, x0.y, x0.z, x0.w, x1.x, x1.y, x1.z, x1.w};
        float ys[8] = {y0.x, y0.y, y0.z, y0.w, y1.x, y1.y, y1.z, y1.w};
#pragma unroll
        for (int q = 0; q < 8; q++) {
            float P  = ps[q] * rp * csv[q];
            float ot = fminf(P, 1.0f);
            sm += ot;
            sx = fmaf(ot, xs[q], sx);
            sy = fmaf(ot, ys[q], sy);
            int jj = j + q;
            if (ot > tv[7] || (ot == tv[7] && jj < tix[7])) {
                tv[7] = ot; tix[7] = jj;
#pragma unroll
                for (int q2 = 7; q2 > 0; --q2) {
                    bool sw = (tv[q2] > tv[q2 - 1]) ||
                              (tv[q2] == tv[q2 - 1] && tix[q2] < tix[q2 - 1]);
                    if (sw) {
                        float fv = tv[q2]; tv[q2] = tv[q2 - 1]; tv[q2 - 1] = fv;
                        int ii = tix[q2]; tix[q2] = tix[q2 - 1]; tix[q2 - 1] = ii;
                    }
                }
            }
        }
    }

    float s0 = sm, s1 = sx, s2 = sy;
#pragma unroll
    for (int o = 16; o; o >>= 1) {
        s0 += __shfl_xor_sync(0xffffffffu, s0, o);
        s1 += __shfl_xor_sync(0xffffffffu, s1, o);
        s2 += __shfl_xor_sync(0xffffffffu, s2, o);
    }
    __shared__ float redm[8], redx[8], redy[8];
    if ((tid & 31) == 0) { redm[tid >> 5] = s0; redx[tid >> 5] = s1; redy[tid >> 5] = s2; }

    __shared__ float sv[2048];
    __shared__ int   si[2048];
#pragma unroll
    for (int t = 0; t < 8; t++) { sv[tid * 8 + t] = tv[t]; si[tid * 8 + t] = tix[t]; }
    __syncthreads();

    for (int step = 128; step >= 1; step >>= 1) {
        if (tid < step) {
            int ia = tid * 8, ib = (tid + step) * 8;
            float av[8], bv[8], ov[8]; int ai[8], bi[8], oi[8];
#pragma unroll
            for (int t = 0; t < 8; t++) {
                av[t] = sv[ia + t]; ai[t] = si[ia + t];
                bv[t] = sv[ib + t]; bi[t] = si[ib + t];
            }
            int pa = 0, pb = 0;
#pragma unroll
            for (int o = 0; o < 8; o++) {
                bool ta = (av[pa] > bv[pb]) || (av[pa] == bv[pb] && ai[pa] <= bi[pb]);
                if (ta) { ov[o] = av[pa]; oi[o] = ai[pa]; pa++; }
                else    { ov[o] = bv[pb]; oi[o] = bi[pb]; pb++; }
            }
#pragma unroll
            for (int t = 0; t < 8; t++) { sv[ia + t] = ov[t]; si[ia + t] = oi[t]; }
        }
        __syncthreads();
    }

    if (tid == 0) {
        float smT = 0, sxT = 0, syT = 0;
#pragma unroll
        for (int w = 0; w < 8; w++) { smT += redm[w]; sxT += redx[w]; syT += redy[w]; }
        float rmass = fmaxf(smT, 1e-8f);
        float valid = fminf(fmaxf(rmass * 8192.0f, 0.0f), 1.0f);
        float top1 = sv[0], top2 = sv[1];
        float pr = fminf(fmaxf(top1 / rmass, 0.0f), 1.0f);
        float pm = fminf(fmaxf((top1 - top2) / rmass, 0.0f), 1.0f);
        float conf = fminf(fmaxf((0.6f * pr + 0.4f * pm) * valid, 0.0f), 1.0f);
        int o = b * NPTS + i;
        g_conf[o] = conf;
        g_base[o * 2]     = sxT / rmass;
        g_base[o * 2 + 1] = syT / rmass;
#pragma unroll
        for (int k = 0; k < 8; k++) {
            g_tki[o * 8 + k] = si[k];
            g_tkl[o * 8 + k] = logf(fmaxf(sv[k], 1e-38f));
        }
    }
}

// ---------------------------------------------------------------------------
// Geo validation: per (b,k) field, 7x7 variance pooling
// ---------------------------------------------------------------------------
__global__ void geo_kernel(const float* __restrict__ posA) {
    int bk = blockIdx.x;
    int b = bk >> 3, k = bk & 7;
    int tid = threadIdx.x;
    __shared__ float dx[NPTS], dy[NPTS];
    for (int n = tid; n < NPTS; n += 256) {
        int idx = g_tki[(b * NPTS + n) * 8 + k];
        float ax = posA[(size_t)(b * NPTS + n) * 2];
        float ay = posA[(size_t)(b * NPTS + n) * 2 + 1];
        dx[n] = g_posBx[b * NPTS + idx] - ax;
        dy[n] = g_posBy[b * NPTS + idx] - ay;
    }
    __syncthreads();
    for (int n = tid; n < NPTS; n += 256) {
        int h = n >> 6, w = n & 63;
        int h0 = max(h - 3, 0), h1 = min(h + 3, 63);
        int w0 = max(w - 3, 0), w1 = min(w + 3, 63);
        float sxv = 0, syv = 0, sxx = 0, syy = 0;
        for (int hh = h0; hh <= h1; hh++) {
            int base = hh * 64;
            for (int ww = w0; ww <= w1; ww++) {
                float vx = dx[base + ww], vy = dy[base + ww];
                sxv += vx; syv += vy;
                sxx = fmaf(vx, vx, sxx);
                syy = fmaf(vy, vy, syy);
            }
        }
        float inv = 1.0f / (float)((h1 - h0 + 1) * (w1 - w0 + 1));
        float mx = sxv * inv, my = syv * inv;
        float vx = fmaxf(sxx * inv - mx * mx, 0.0f);
        float vy = fmaxf(syy * inv - my * my, 0.0f);
        g_geo[(b * NPTS + n) * 8 + k] = 1.0f / (1.0f + (vx + vy) * 100.0f);
    }
}

// ---------------------------------------------------------------------------
// Final blend
// ---------------------------------------------------------------------------
__global__ void final_kernel(float* __restrict__ out) {
    int t = blockIdx.x * 128 + threadIdx.x;
    int b = t >> 12, n = t & 4095;
    int o = b * NPTS + n;
    float gwv = g_params[2];
    float lc[8]; int id[8];
    float m = -1e30f;
#pragma unroll
    for (int k = 0; k < 8; k++) {
        lc[k] = g_tkl[o * 8 + k] + gwv * g_geo[o * 8 + k];
        id[k] = g_tki[o * 8 + k];
        m = fmaxf(m, lc[k]);
    }
    float ws = 0, rx = 0, ry = 0;
#pragma unroll
    for (int k = 0; k < 8; k++) {
        float w = fexpf(fmaxf(lc[k] - m, -80.0f));
        ws += w;
        rx = fmaf(w, g_posBx[b * NPTS + id[k]], rx);
        ry = fmaf(w, g_posBy[b * NPTS + id[k]], ry);
    }
    rx /= ws; ry /= ws;
    float conf = g_conf[o];
    out[o * 2]     = conf * rx + (1.0f - conf) * g_base[o * 2];
    out[o * 2 + 1] = conf * ry + (1.0f - conf) * g_base[o * 2 + 1];
}

// ---------------------------------------------------------------------------
extern "C" void kernel_launch(void* const* d_in, const int* in_sizes, int n_in,
                              void* d_out, int out_size) {
    const float* fA   = (const float*)d_in[0];
    const float* fB   = (const float*)d_in[1];
    const float* pA   = (const float*)d_in[2];
    const float* pB   = (const float*)d_in[3];
    const float* dust = (const float*)d_in[4];
    const float* geow = (const float*)d_in[5];
    const float* temp = (const float*)d_in[6];
    float* out = (float*)d_out;

    prep_kernel<<<33, 256>>>(dust, geow, temp, pB);
    norm_kernel<<<2048, 256>>>(fA, fB);
    gemm_exp_kernel<<<dim3(32, 32, BATCH), 256>>>();
    for (int it = 0; it < ITERS; ++it) {
        sink_fused<<<dim3(64, BATCH), 512>>>();
        sink_finish<<<BATCH, 1024>>>();
    }
    stats_kernel<<<dim3(NPTS, BATCH), 256>>>();
    geo_kernel<<<BATCH * TOPK, 256>>>(pA);
    final_kernel<<<64, 128>>>(out);
}